// round 13
// baseline (speedup 1.0000x reference)
#include <cuda_runtime.h>

// QLIFSpike: leaky-integrate-fire with hard reset + membrane quantization.
// x: [B,T,C,H,W] fp32, mask: [B,T,C] int32, conv_input: [1] fp32 (unused).
// out: spikes [B,T,C,H,W] fp32.
//
// One thread owns one (b, c, 4-wide spatial chunk) neuron group and carries
// the membrane potential in registers across the T=10 sequential steps.
// Pure streaming: each x element read once, each out element written once.

#define BB 32
#define TT 10
#define CC 128
#define HW 1024           // 32*32
#define HW4 256           // HW / 4 (float4 chunks)

__device__ __forceinline__ float qlif_step(float& mem, float xi) {
    mem = fmaf(mem, 0.5f, xi);            // leaky integrate: mem*TAU + x
    float spike = (mem > 1.0f) ? 1.0f : 0.0f;  // zif(mem - THRESH)
    mem = (mem > 1.0f) ? 0.0f : mem;      // hard reset
    // qmem: clip(rint(mem), -3, 1); rintf = round-to-nearest-even matches jnp.round
    mem = fminf(fmaxf(rintf(mem), -3.0f), 1.0f);
    return spike;
}

__global__ __launch_bounds__(256)
void qlif_spike_kernel(const float4* __restrict__ x,
                       const int*    __restrict__ mask,
                       float4*       __restrict__ out) {
    const int idx = blockIdx.x * blockDim.x + threadIdx.x;  // 0 .. B*C*HW4-1
    const int p  = idx & (HW4 - 1);       // spatial float4 index within plane
    const int bc = idx >> 8;              // / HW4
    const int c  = bc & (CC - 1);
    const int b  = bc >> 7;               // / CC

    float4 mem = make_float4(0.f, 0.f, 0.f, 0.f);

    #pragma unroll
    for (int t = 0; t < TT; ++t) {
        const long plane = (long)(b * TT + t) * CC + c;   // index into [B*T*C] planes
        const float mk = (float)__ldg(&mask[plane]);      // L2-resident, 1024x reuse
        float4 xi = x[plane * HW4 + p];

        float4 sp;
        sp.x = qlif_step(mem.x, xi.x * mk);
        sp.y = qlif_step(mem.y, xi.y * mk);
        sp.z = qlif_step(mem.z, xi.z * mk);
        sp.w = qlif_step(mem.w, xi.w * mk);

        out[plane * HW4 + p] = sp;
    }
}

extern "C" void kernel_launch(void* const* d_in, const int* in_sizes, int n_in,
                              void* d_out, int out_size) {
    const float4* x    = (const float4*)d_in[0];
    const int*    mask = (const int*)d_in[1];
    float4*       out  = (float4*)d_out;

    const int total_threads = BB * CC * HW4;   // 1,048,576
    const int block = 256;
    const int grid  = total_threads / block;   // 4096

    qlif_spike_kernel<<<grid, block>>>(x, mask, out);
}

// round 14
// speedup vs baseline: 1.2271x; 1.2271x over previous
#include <cuda_runtime.h>

// QLIFSpike: leaky-integrate-fire with hard reset + membrane quantization.
// x: [B,T,C,H,W] fp32, mask: [B,T,C] int32, conv_input: [1] fp32 (unused).
// out: spikes [B,T,C,H,W] fp32.
//
// One thread owns one (b, c, 4-wide spatial chunk) and carries the membrane
// in registers across T=10 steps.
//
// Key optimization: mask is per-(b,t,c) plane and warp-uniform (each warp's
// 128 floats sit inside one 1024-float plane). When mask==0 the plane's input
// contributes exactly 0, so we SKIP the x load entirely (the membrane still
// decays/quantizes, and with quantized mem<=1, mem*0.5<1 so no spike —
// bit-identical to the reference). This cuts DRAM reads ~50%.

#define BB 32
#define TT 10
#define CC 128
#define HW4 256           // (32*32) / 4 float4 chunks per plane

__device__ __forceinline__ float qlif_step(float& mem, float xi) {
    mem = fmaf(mem, 0.5f, xi);                 // leaky integrate: mem*TAU + x
    float spike = (mem > 1.0f) ? 1.0f : 0.0f;  // zif(mem - THRESH)
    mem = (mem > 1.0f) ? 0.0f : mem;           // hard reset
    // qmem: clip(rint(mem), -3, 1); rintf = round-half-even matches jnp.round
    mem = fminf(fmaxf(rintf(mem), -3.0f), 1.0f);
    return spike;
}

__global__ __launch_bounds__(256)
void qlif_spike_kernel(const float4* __restrict__ x,
                       const int*    __restrict__ mask,
                       float4*       __restrict__ out) {
    const int idx = blockIdx.x * blockDim.x + threadIdx.x;  // 0 .. B*C*HW4-1
    const int p  = idx & (HW4 - 1);       // spatial float4 index within plane
    const int bc = idx >> 8;              // / HW4
    const int c  = bc & (CC - 1);
    const int b  = bc >> 7;               // / CC

    float4 mem = make_float4(0.f, 0.f, 0.f, 0.f);

    #pragma unroll
    for (int t = 0; t < TT; ++t) {
        const int plane = (b * TT + t) * CC + c;   // index into [B*T*C] planes
        const int mk = __ldg(&mask[plane]);        // warp-uniform, L2-resident

        // Warp-uniform skip: mask==0 plane contributes xi=0 -> no DRAM read.
        float4 xi = make_float4(0.f, 0.f, 0.f, 0.f);
        if (mk) {
            xi = __ldcs(&x[plane * HW4 + p]);      // streaming, evict-first
        }

        float4 sp;
        sp.x = qlif_step(mem.x, xi.x);
        sp.y = qlif_step(mem.y, xi.y);
        sp.z = qlif_step(mem.z, xi.z);
        sp.w = qlif_step(mem.w, xi.w);

        __stcs(&out[plane * HW4 + p], sp);         // streaming store
    }
}

extern "C" void kernel_launch(void* const* d_in, const int* in_sizes, int n_in,
                              void* d_out, int out_size) {
    const float4* x    = (const float4*)d_in[0];
    const int*    mask = (const int*)d_in[1];
    float4*       out  = (float4*)d_out;

    const int total_threads = BB * CC * HW4;   // 1,048,576
    const int block = 256;
    const int grid  = total_threads / block;   // 4096

    qlif_spike_kernel<<<grid, block>>>(x, mask, out);
}

// round 15
// speedup vs baseline: 1.2297x; 1.0021x over previous
#include <cuda_runtime.h>

// QLIFSpike: leaky-integrate-fire with hard reset + membrane quantization.
// x: [B,T,C,H,W] fp32, mask: [B,T,C] int32, conv_input: [1] fp32 (unused).
// out: spikes [B,T,C,H,W] fp32.
//
// One thread owns one (b, c, 4-wide spatial chunk) and carries the membrane
// in registers across T=10 steps.
//
// Key optimization: mask is per-(b,t,c) plane and warp-uniform (each warp's
// 128 floats sit inside one 1024-float plane). When mask==0 the plane's input
// contributes exactly 0, so we SKIP the x load entirely (the membrane still
// decays/quantizes, and with quantized mem<=1, mem*0.5<1 so no spike —
// bit-identical to the reference). This cuts DRAM reads ~50%.

#define BB 32
#define TT 10
#define CC 128
#define HW4 256           // (32*32) / 4 float4 chunks per plane

__device__ __forceinline__ float qlif_step(float& mem, float xi) {
    mem = fmaf(mem, 0.5f, xi);                 // leaky integrate: mem*TAU + x
    float spike = (mem > 1.0f) ? 1.0f : 0.0f;  // zif(mem - THRESH)
    mem = (mem > 1.0f) ? 0.0f : mem;           // hard reset
    // qmem: clip(rint(mem), -3, 1); rintf = round-half-even matches jnp.round
    mem = fminf(fmaxf(rintf(mem), -3.0f), 1.0f);
    return spike;
}

__global__ __launch_bounds__(256)
void qlif_spike_kernel(const float4* __restrict__ x,
                       const int*    __restrict__ mask,
                       float4*       __restrict__ out) {
    const int idx = blockIdx.x * blockDim.x + threadIdx.x;  // 0 .. B*C*HW4-1
    const int p  = idx & (HW4 - 1);       // spatial float4 index within plane
    const int bc = idx >> 8;              // / HW4
    const int c  = bc & (CC - 1);
    const int b  = bc >> 7;               // / CC

    float4 mem = make_float4(0.f, 0.f, 0.f, 0.f);

    #pragma unroll
    for (int t = 0; t < TT; ++t) {
        const int plane = (b * TT + t) * CC + c;   // index into [B*T*C] planes
        const int mk = __ldg(&mask[plane]);        // warp-uniform, L2-resident

        // Warp-uniform skip: mask==0 plane contributes xi=0 -> no DRAM read.
        float4 xi = make_float4(0.f, 0.f, 0.f, 0.f);
        if (mk) {
            xi = __ldcs(&x[plane * HW4 + p]);      // streaming, evict-first
        }

        float4 sp;
        sp.x = qlif_step(mem.x, xi.x);
        sp.y = qlif_step(mem.y, xi.y);
        sp.z = qlif_step(mem.z, xi.z);
        sp.w = qlif_step(mem.w, xi.w);

        __stcs(&out[plane * HW4 + p], sp);         // streaming store
    }
}

extern "C" void kernel_launch(void* const* d_in, const int* in_sizes, int n_in,
                              void* d_out, int out_size) {
    const float4* x    = (const float4*)d_in[0];
    const int*    mask = (const int*)d_in[1];
    float4*       out  = (float4*)d_out;

    const int total_threads = BB * CC * HW4;   // 1,048,576
    const int block = 256;
    const int grid  = total_threads / block;   // 4096

    qlif_spike_kernel<<<grid, block>>>(x, mask, out);
}